// round 5
// baseline (speedup 1.0000x reference)
#include <cuda_runtime.h>
#include <cuda_bf16.h>
#include <stdint.h>

#define NMAX 50000
#define EMAX 600000
#define D 128
#define NPART 4

// ======================= device scratch (no allocation) =======================
// f buffers: interleaved hi/lo bf16 pairs. Per node: 32 uint4; uint4 = {hi(c01),lo(c01),hi(c23),lo(c23)}
__device__ uint4  g_fA[NMAX * 32];
__device__ uint4  g_fB[NMAX * 32];
__device__ uint4  g_s [NMAX * 32];            // normalized neighbor sum, same layout
__device__ uint4  g_Whi4[8 * 2048];           // 8 weight matrices bf16 hi [l*2 + {0:W1,1:W0}]
__device__ uint4  g_Wlo4[8 * 2048];
__device__ int    g_cnt[NMAX];
__device__ int    g_cursor[NMAX];
__device__ int    g_rowptr[NMAX + 1];
__device__ float  g_invdeg[NMAX];
__device__ int    g_adj[2 * EMAX];

// ======================= bf16 split helpers =======================
__device__ __forceinline__ void split2(float a, float b, uint32_t& hi, uint32_t& lo) {
    __nv_bfloat16 ha = __float2bfloat16_rn(a), hb = __float2bfloat16_rn(b);
    float ra = a - __bfloat162float(ha), rb = b - __bfloat162float(hb);
    __nv_bfloat162 H = __halves2bfloat162(ha, hb);
    __nv_bfloat162 L = __halves2bfloat162(__float2bfloat16_rn(ra), __float2bfloat16_rn(rb));
    hi = *(uint32_t*)&H;
    lo = *(uint32_t*)&L;
}

// ======================= setup kernels =======================
__global__ void k_zero(int n) {
    int i = blockIdx.x * blockDim.x + threadIdx.x;
    if (i < n) g_cnt[i] = 0;
}

__global__ void k_count(const int* __restrict__ edges, int E) {
    int e = blockIdx.x * blockDim.x + threadIdx.x;
    if (e < E) {
        atomicAdd(&g_cnt[edges[2 * e]], 1);
        atomicAdd(&g_cnt[edges[2 * e + 1]], 1);
    }
}

__global__ void k_scan(int n) {
    __shared__ int ss[1024];
    int t = threadIdx.x;
    int chunk = (n + 1023) >> 10;
    int b = t * chunk;
    int e = min(b + chunk, n);
    int s = 0;
    for (int i = b; i < e; i++) s += g_cnt[i];
    ss[t] = s;
    __syncthreads();
    for (int off = 1; off < 1024; off <<= 1) {
        int add = (t >= off) ? ss[t - off] : 0;
        __syncthreads();
        ss[t] += add;
        __syncthreads();
    }
    int run = (t == 0) ? 0 : ss[t - 1];
    for (int i = b; i < e; i++) {
        g_rowptr[i] = run;
        g_cursor[i] = run;
        int c = g_cnt[i];
        g_invdeg[i] = 1.0f / (float)(c > 0 ? c : 1);
        run += c;
    }
    if (t == 1023) g_rowptr[n] = ss[1023];
}

__global__ void k_fill(const int* __restrict__ edges, int E) {
    int e = blockIdx.x * blockDim.x + threadIdx.x;
    if (e < E) {
        int s = edges[2 * e];
        int d = edges[2 * e + 1];
        g_adj[atomicAdd(&g_cursor[s], 1)] = d;
        g_adj[atomicAdd(&g_cursor[d], 1)] = s;
    }
}

// per-node insertion sort -> deterministic float summation order across replays
__global__ void k_sortseg(int n) {
    int i = blockIdx.x * blockDim.x + threadIdx.x;
    if (i >= n) return;
    int b = g_rowptr[i], e = g_rowptr[i + 1];
    for (int j = b + 1; j < e; j++) {
        int key = g_adj[j];
        int k = j - 1;
        while (k >= b && g_adj[k] > key) { g_adj[k + 1] = g_adj[k]; --k; }
        g_adj[k + 1] = key;
    }
}

// ======================= conversion =======================
__global__ void k_conv(const float* __restrict__ features,
                       const float* __restrict__ W0f, const float* __restrict__ W1f,
                       const float* __restrict__ W0h, const float* __restrict__ W1h,
                       int Nn) {
    int i = blockIdx.x * blockDim.x + threadIdx.x;
    if (i < Nn * 32) {
        float4 v = ((const float4*)features)[i];
        uint32_t h0, l0, h1, l1;
        split2(v.x, v.y, h0, l0);
        split2(v.z, v.w, h1, l1);
        g_fA[i] = make_uint4(h0, l0, h1, l1);
    }
    if (i < 8 * 4096) {
        int m = i >> 12;            // matrix 0..7 (4096 float4 each)
        int off = i & 4095;
        int l = m >> 1;
        int isW0 = m & 1;
        const float* src = (l == 0) ? (isW0 ? W0f : W1f)
                                    : (isW0 ? W0h + (size_t)(l - 1) * D * D
                                            : W1h + (size_t)(l - 1) * D * D);
        float4 v = ((const float4*)src)[off];
        uint32_t h0, l0, h1, l1;
        split2(v.x, v.y, h0, l0);
        split2(v.z, v.w, h1, l1);
        ((uint2*)g_Whi4)[(size_t)m * 4096 + off] = make_uint2(h0, h1);
        ((uint2*)g_Wlo4)[(size_t)m * 4096 + off] = make_uint2(l0, l1);
    }
}

// ======================= gather: s = (1/deg) * sum_{j in N(i)} f_j =======================
__device__ __forceinline__ void acc4(float4& a, uint4 v) {
    float2 pH = __bfloat1622float2(*(__nv_bfloat162*)&v.x);
    float2 pL = __bfloat1622float2(*(__nv_bfloat162*)&v.y);
    float2 qH = __bfloat1622float2(*(__nv_bfloat162*)&v.z);
    float2 qL = __bfloat1622float2(*(__nv_bfloat162*)&v.w);
    a.x += pH.x + pL.x; a.y += pH.y + pL.y;
    a.z += qH.x + qL.x; a.w += qH.y + qL.y;
}

__global__ void k_gather(const uint4* __restrict__ f, uint4* __restrict__ sarr,
                         int nodeStart, int nodeEnd) {
    int node = nodeStart + ((blockIdx.x * blockDim.x + threadIdx.x) >> 5);
    if (node >= nodeEnd) return;
    int lane = threadIdx.x & 31;
    int b = g_rowptr[node], e = g_rowptr[node + 1];
    float4 a0 = make_float4(0.f, 0.f, 0.f, 0.f);
    float4 a1 = a0, a2 = a0, a3 = a0;
    int p = b;
    for (; p + 4 <= e; p += 4) {
        uint4 v0 = f[(size_t)g_adj[p] * 32 + lane];
        uint4 v1 = f[(size_t)g_adj[p + 1] * 32 + lane];
        uint4 v2 = f[(size_t)g_adj[p + 2] * 32 + lane];
        uint4 v3 = f[(size_t)g_adj[p + 3] * 32 + lane];
        acc4(a0, v0); acc4(a1, v1); acc4(a2, v2); acc4(a3, v3);
    }
    for (; p < e; ++p) acc4(a0, f[(size_t)g_adj[p] * 32 + lane]);
    float sc = g_invdeg[node];
    float4 r;
    r.x = (a0.x + a1.x + a2.x + a3.x) * sc;
    r.y = (a0.y + a1.y + a2.y + a3.y) * sc;
    r.z = (a0.z + a1.z + a2.z + a3.z) * sc;
    r.w = (a0.w + a1.w + a2.w + a3.w) * sc;
    uint32_t h0, l0, h1, l1;
    split2(r.x, r.y, h0, l0);
    split2(r.z, r.w, h1, l1);
    sarr[(size_t)node * 32 + lane] = make_uint4(h0, l0, h1, l1);
}

// ======================= fused GEMM: out = f@W0^T + s@W1^T + b (+res)(relu) =====
#define SROW 272
#define STILE (128 * SROW)                 // 34816 B per 128x128 bf16 tile
#define SMEM_MM_TOTAL (4 * STILE)          // 139264 B

__device__ __forceinline__ uint32_t smem_to_u32(const void* smem_ptr) {
    uint32_t addr;
    asm("{ .reg .u64 tmp; cvta.to.shared.u64 tmp, %1; cvt.u32.u64 %0, tmp; }"
        : "=r"(addr) : "l"(smem_ptr));
    return addr;
}

__device__ __forceinline__ void ldm_x4(uint32_t* r, uint32_t addr) {
    asm volatile("ldmatrix.sync.aligned.m8n8.x4.shared.b16 {%0,%1,%2,%3}, [%4];"
        : "=r"(r[0]), "=r"(r[1]), "=r"(r[2]), "=r"(r[3]) : "r"(addr));
}

__device__ __forceinline__ void mma16816(float* c, const uint32_t* a, const uint32_t* b) {
    asm volatile(
        "mma.sync.aligned.m16n8k16.row.col.f32.bf16.bf16.f32 "
        "{%0,%1,%2,%3}, {%4,%5,%6,%7}, {%8,%9}, {%0,%1,%2,%3};"
        : "+f"(c[0]), "+f"(c[1]), "+f"(c[2]), "+f"(c[3])
        : "r"(a[0]), "r"(a[1]), "r"(a[2]), "r"(a[3]), "r"(b[0]), "r"(b[1]));
}

// mode 0: out = v            -> fout (split hi/lo, interleaved)
// mode 1: out = relu(v)      -> fout
// mode 2: out = relu(v+res)  -> dout fp32
__global__ void __launch_bounds__(512, 1)
k_mmf(const uint4* __restrict__ fin, const uint4* __restrict__ sin,
      const uint4* __restrict__ w0hi, const uint4* __restrict__ w0lo,
      const uint4* __restrict__ w1hi, const uint4* __restrict__ w1lo,
      const float* __restrict__ bias, const float* __restrict__ res,
      uint32_t* __restrict__ fout, float* __restrict__ dout,
      int rowStart, int M, int mode) {
    extern __shared__ char smem[];
    const int tid = threadIdx.x;
    const int wid = tid >> 5;
    const int lane = tid & 31;
    const int wm = wid >> 2;       // 0..3 : 32-row strip
    const int wn = wid & 3;        // 0..3 : 32-col strip
    const int rowBase = rowStart + blockIdx.x * 128;

    uint32_t sb = smem_to_u32(smem);
    const uint32_t aRowOff = (uint32_t)(wm * 32 + (lane & 15)) * SROW + ((lane >> 4) << 4);
    const uint32_t bRowCore = (uint32_t)(((lane >> 4) << 3) + (lane & 7)) * SROW
                            + (((lane >> 3) & 1) << 4);

    float acc[2][4][4];
#pragma unroll
    for (int mt = 0; mt < 2; mt++)
#pragma unroll
        for (int nt = 0; nt < 4; nt++)
#pragma unroll
            for (int q = 0; q < 4; q++) acc[mt][nt][q] = 0.f;

#pragma unroll 1
    for (int ph = 0; ph < 2; ph++) {
        const uint4* A  = ph ? sin  : fin;
        const uint4* WH = ph ? w1hi : w0hi;
        const uint4* WL = ph ? w1lo : w0lo;
        if (ph) __syncthreads();   // all warps done with previous operands

        // A: 4096 interleaved uint4 -> AH/AL tiles (8B stores)
#pragma unroll
        for (int it = 0; it < 8; it++) {
            int i = tid + 512 * it;
            int r = i >> 5, c8 = i & 31;
            uint4 v = (rowBase + r < M) ? A[(size_t)(rowBase + r) * 32 + c8]
                                        : make_uint4(0, 0, 0, 0);
            uint32_t off = (uint32_t)r * SROW + (uint32_t)c8 * 8;
            *(uint2*)(smem + off)         = make_uint2(v.x, v.z);   // hi
            *(uint2*)(smem + STILE + off) = make_uint2(v.y, v.w);   // lo
        }
        // W: 2048 uint4 each
#pragma unroll
        for (int it = 0; it < 4; it++) {
            int i = tid + 512 * it;
            int r = i >> 4, c16 = i & 15;
            uint32_t off = (uint32_t)r * SROW + (uint32_t)c16 * 16;
            *(uint4*)(smem + 2 * STILE + off) = WH[i];
            *(uint4*)(smem + 3 * STILE + off) = WL[i];
        }
        __syncthreads();

        uint32_t aHi = sb, aLo = sb + STILE;
        uint32_t wHi = sb + 2 * STILE, wLo = sb + 3 * STILE;
#pragma unroll 1
        for (int t = 0; t < 3; t++) {
            uint32_t aT = (t == 2) ? aLo : aHi;     // hi, hi, lo
            uint32_t wT = (t == 1) ? wLo : wHi;     // hi, lo, hi
#pragma unroll
            for (int ks = 0; ks < 8; ks++) {
                uint32_t kb = (uint32_t)ks * 32;
                uint32_t a[2][4];
                ldm_x4(a[0], aT + aRowOff + kb);
                ldm_x4(a[1], aT + aRowOff + 16 * SROW + kb);
                uint32_t bfr[4][2];
#pragma unroll
                for (int np = 0; np < 2; np++) {
                    uint32_t tmp[4];
                    ldm_x4(tmp, wT + (uint32_t)(wn * 32 + np * 16) * SROW + bRowCore + kb);
                    bfr[np * 2][0] = tmp[0]; bfr[np * 2][1] = tmp[1];
                    bfr[np * 2 + 1][0] = tmp[2]; bfr[np * 2 + 1][1] = tmp[3];
                }
#pragma unroll
                for (int mt = 0; mt < 2; mt++)
#pragma unroll
                    for (int nt = 0; nt < 4; nt++)
                        mma16816(acc[mt][nt], a[mt], bfr[nt]);
            }
        }
    }

    // epilogue
    const int g = lane >> 2, tg = lane & 3;
#pragma unroll
    for (int mt = 0; mt < 2; mt++) {
        int r0 = rowBase + wm * 32 + mt * 16 + g;
#pragma unroll
        for (int half = 0; half < 2; half++) {
            int row = r0 + half * 8;
            if (row >= M) continue;
#pragma unroll
            for (int nt = 0; nt < 4; nt++) {
                int col = wn * 32 + nt * 8 + tg * 2;
                float v0 = acc[mt][nt][half * 2 + 0] + bias[col];
                float v1 = acc[mt][nt][half * 2 + 1] + bias[col + 1];
                if (mode == 2) {
                    v0 += res[(size_t)row * 128 + col];
                    v1 += res[(size_t)row * 128 + col + 1];
                }
                if (mode >= 1) { v0 = fmaxf(v0, 0.f); v1 = fmaxf(v1, 0.f); }
                if (mode == 2) {
                    *(float2*)(dout + (size_t)row * 128 + col) = make_float2(v0, v1);
                } else {
                    uint32_t hi, lo;
                    split2(v0, v1, hi, lo);
                    *(uint2*)(fout + (size_t)row * 128 + col) = make_uint2(hi, lo);
                }
            }
        }
    }
}

// ======================= launch =======================
extern "C" void kernel_launch(void* const* d_in, const int* in_sizes, int n_in,
                              void* d_out, int out_size) {
    const float* features = (const float*)d_in[0];
    const int*   edges    = (const int*)d_in[1];
    const float* W0f = (const float*)d_in[3];
    const float* W1f = (const float*)d_in[4];
    const float* bf  = (const float*)d_in[5];
    const float* W0h = (const float*)d_in[6];
    const float* W1h = (const float*)d_in[7];
    const float* bh  = (const float*)d_in[8];

    int Nn = in_sizes[0] / D;
    int Ee = in_sizes[1] / 2;

    uint4 *fA, *fB, *sbuf, *whi, *wlo;
    cudaGetSymbolAddress((void**)&fA,   g_fA);
    cudaGetSymbolAddress((void**)&fB,   g_fB);
    cudaGetSymbolAddress((void**)&sbuf, g_s);
    cudaGetSymbolAddress((void**)&whi,  g_Whi4);
    cudaGetSymbolAddress((void**)&wlo,  g_Wlo4);

    cudaFuncSetAttribute(k_mmf, cudaFuncAttributeMaxDynamicSharedMemorySize, SMEM_MM_TOTAL);

    cudaStream_t s0 = (cudaStream_t)0;   // capture-origin (default) stream
    cudaStream_t s1;
    cudaStreamCreateWithFlags(&s1, cudaStreamNonBlocking);

    cudaEvent_t evFork, evConv, evM[4], evG[4][NPART];
    cudaEventCreateWithFlags(&evFork, cudaEventDisableTiming);
    cudaEventCreateWithFlags(&evConv, cudaEventDisableTiming);
    for (int l = 0; l < 4; l++) {
        cudaEventCreateWithFlags(&evM[l], cudaEventDisableTiming);
        for (int p = 0; p < NPART; p++)
            cudaEventCreateWithFlags(&evG[l][p], cudaEventDisableTiming);
    }

    // fork s1 from the capture stream
    cudaEventRecord(evFork, s0);
    cudaStreamWaitEvent(s1, evFork, 0);

    // CSR chain on s1 (launch order keeps k_fill as 4th kernel for ncu)
    k_zero   <<<(Nn + 255) / 256, 256, 0, s1>>>(Nn);
    k_count  <<<(Ee + 255) / 256, 256, 0, s1>>>(edges, Ee);
    k_scan   <<<1, 1024, 0, s1>>>(Nn);
    k_fill   <<<(Ee + 255) / 256, 256, 0, s1>>>(edges, Ee);
    k_sortseg<<<(Nn + 127) / 128, 128, 0, s1>>>(Nn);

    // conversion on s0 (overlaps CSR build)
    int vblocks = (Nn * 32 + 255) / 256;
    k_conv<<<vblocks, 256, 0, s0>>>(features, W0f, W1f, W0h, W1h, Nn);
    cudaEventRecord(evConv, s0);
    cudaStreamWaitEvent(s1, evConv, 0);   // gathers need fA

    const int totTiles = (Nn + 127) / 128;
    const int TPP = (totTiles + NPART - 1) / NPART;

    uint4* fin = fA;
    uint4* fout = fB;
    for (int l = 0; l < 4; l++) {
        const uint4* W0h_ = whi + (size_t)(2 * l + 1) * 2048;
        const uint4* W0l_ = wlo + (size_t)(2 * l + 1) * 2048;
        const uint4* W1h_ = whi + (size_t)(2 * l) * 2048;
        const uint4* W1l_ = wlo + (size_t)(2 * l) * 2048;
        const float* bb = (l == 0) ? bf : bh + (size_t)(l - 1) * D;
        int mode = (l == 0) ? 0 : (l == 3 ? 2 : 1);

        for (int p = 0; p < NPART; p++) {
            int t0 = p * TPP, t1 = min(t0 + TPP, totTiles);
            if (t0 >= t1) continue;
            int n0 = t0 * 128;
            int n1 = min(t1 * 128, Nn);
            int gblocks = ((n1 - n0) * 32 + 255) / 256;
            k_gather<<<gblocks, 256, 0, s1>>>(fin, sbuf, n0, n1);
            cudaEventRecord(evG[l][p], s1);
            cudaStreamWaitEvent(s0, evG[l][p], 0);
            k_mmf<<<t1 - t0, 512, SMEM_MM_TOTAL, s0>>>(
                fin, sbuf, W0h_, W0l_, W1h_, W1l_, bb, features,
                (uint32_t*)fout, (float*)d_out, n0, Nn, mode);
        }
        cudaEventRecord(evM[l], s0);
        if (l < 3) cudaStreamWaitEvent(s1, evM[l], 0);  // next-layer gathers need all f_{l+1}

        uint4* t = fin; fin = fout; fout = t;
    }
}

// round 6
// speedup vs baseline: 1.0991x; 1.0991x over previous
#include <cuda_runtime.h>
#include <cuda_bf16.h>
#include <stdint.h>

#define NMAX 50000
#define EMAX 600000
#define D 128

// ======================= device scratch (no allocation) =======================
__device__ uint4  g_fhi4[NMAX * D / 8];       // bf16 hi of layer input
__device__ uint4  g_flo4[NMAX * D / 8];       // bf16 lo
__device__ uint4  g_Whi4[8 * D * D / 8];      // 8 weight matrices bf16 hi [l*2 + {0:W1,1:W0}]
__device__ uint4  g_Wlo4[8 * D * D / 8];
__device__ float4 g_hA[NMAX * D / 4];         // h ping
__device__ float4 g_hB[NMAX * D / 4];         // h pong
__device__ float4 g_rawA[NMAX * D / 4];       // raw ping
__device__ float4 g_rawB[NMAX * D / 4];       // raw pong
__device__ int    g_cnt[NMAX];
__device__ int    g_cursor[NMAX];
__device__ int    g_rowptr[NMAX + 1];
__device__ float  g_invdeg[NMAX];
__device__ int    g_adj[2 * EMAX];

// ======================= bf16 hi/lo split =======================
__device__ __forceinline__ void split4(float4 v, uint2& hi, uint2& lo) {
    __nv_bfloat16 hx = __float2bfloat16_rn(v.x);
    __nv_bfloat16 hy = __float2bfloat16_rn(v.y);
    __nv_bfloat16 hz = __float2bfloat16_rn(v.z);
    __nv_bfloat16 hw = __float2bfloat16_rn(v.w);
    __nv_bfloat16 lx = __float2bfloat16_rn(v.x - __bfloat162float(hx));
    __nv_bfloat16 ly = __float2bfloat16_rn(v.y - __bfloat162float(hy));
    __nv_bfloat16 lz = __float2bfloat16_rn(v.z - __bfloat162float(hz));
    __nv_bfloat16 lw = __float2bfloat16_rn(v.w - __bfloat162float(hw));
    __nv_bfloat162 h01 = __halves2bfloat162(hx, hy);
    __nv_bfloat162 h23 = __halves2bfloat162(hz, hw);
    __nv_bfloat162 l01 = __halves2bfloat162(lx, ly);
    __nv_bfloat162 l23 = __halves2bfloat162(lz, lw);
    hi.x = *(uint32_t*)&h01; hi.y = *(uint32_t*)&h23;
    lo.x = *(uint32_t*)&l01; lo.y = *(uint32_t*)&l23;
}

__global__ void k_conv(const float* __restrict__ features,
                       const float* __restrict__ W0f, const float* __restrict__ W1f,
                       const float* __restrict__ W0h, const float* __restrict__ W1h,
                       int Nn) {
    int i = blockIdx.x * blockDim.x + threadIdx.x;
    if (i < Nn * 32) {
        float4 v = ((const float4*)features)[i];
        uint2 hi, lo;
        split4(v, hi, lo);
        ((uint2*)g_fhi4)[i] = hi;
        ((uint2*)g_flo4)[i] = lo;
    }
    if (i < 8 * 4096) {
        int m = i >> 12;            // matrix 0..7 (4096 float4 each)
        int off = i & 4095;
        int l = m >> 1;
        int isW0 = m & 1;
        const float* src = (l == 0) ? (isW0 ? W0f : W1f)
                                    : (isW0 ? W0h + (size_t)(l - 1) * D * D
                                            : W1h + (size_t)(l - 1) * D * D);
        float4 v = ((const float4*)src)[off];
        uint2 hi, lo;
        split4(v, hi, lo);
        ((uint2*)g_Whi4)[(size_t)m * 4096 + off] = hi;
        ((uint2*)g_Wlo4)[(size_t)m * 4096 + off] = lo;
    }
}

// ======================= CSR build =======================
__global__ void k_count(const int* __restrict__ edges, int E) {
    int e = blockIdx.x * blockDim.x + threadIdx.x;
    if (e < E) {
        atomicAdd(&g_cnt[edges[2 * e]], 1);
        atomicAdd(&g_cnt[edges[2 * e + 1]], 1);
    }
}

__global__ void k_scan(int n) {
    __shared__ int ss[1024];
    int t = threadIdx.x;
    int chunk = (n + 1023) >> 10;
    int b = t * chunk;
    int e = min(b + chunk, n);
    int s = 0;
    for (int i = b; i < e; i++) s += g_cnt[i];
    ss[t] = s;
    __syncthreads();
    for (int off = 1; off < 1024; off <<= 1) {
        int add = (t >= off) ? ss[t - off] : 0;
        __syncthreads();
        ss[t] += add;
        __syncthreads();
    }
    int run = (t == 0) ? 0 : ss[t - 1];
    for (int i = b; i < e; i++) {
        g_rowptr[i] = run;
        g_cursor[i] = run;
        int c = g_cnt[i];
        g_invdeg[i] = 1.0f / (float)(c > 0 ? c : 1);
        run += c;
    }
    if (t == 1023) g_rowptr[n] = ss[1023];
}

__global__ void k_fill(const int* __restrict__ edges, int E) {
    int e = blockIdx.x * blockDim.x + threadIdx.x;
    if (e < E) {
        int s = edges[2 * e];
        int d = edges[2 * e + 1];
        g_adj[atomicAdd(&g_cursor[s], 1)] = d;
        g_adj[atomicAdd(&g_cursor[d], 1)] = s;
    }
}

// per-node insertion sort -> deterministic float summation order across replays
__global__ void k_sortseg(int n) {
    int i = blockIdx.x * blockDim.x + threadIdx.x;
    if (i >= n) return;
    int b = g_rowptr[i], e = g_rowptr[i + 1];
    for (int j = b + 1; j < e; j++) {
        int key = g_adj[j];
        int k = j - 1;
        while (k >= b && g_adj[k] > key) { g_adj[k + 1] = g_adj[k]; --k; }
        g_adj[k + 1] = key;
    }
}

// ======================= tensor-core fused GEMM (mma.sync bf16) ================
// 512 threads: warps 0-7 compute h = A@W1^T, warps 8-15 compute raw = A@W0^T.
// A split hi/lo, W split hi/lo, 3-term compensation (hi*hi + hi*lo + lo*hi).
#define SROW 272
#define STILE (128 * SROW)                 // 34816 B per 128x128 bf16 tile
#define SM_A_HI  0
#define SM_A_LO  (STILE)
#define SM_W1HI  (2 * STILE)
#define SM_W1LO  (3 * STILE)
#define SM_W0HI  (4 * STILE)
#define SM_W0LO  (5 * STILE)
#define SMEM_MM_TOTAL (6 * STILE)          // 208896 B

__device__ __forceinline__ uint32_t smem_to_u32(const void* smem_ptr) {
    uint32_t addr;
    asm("{ .reg .u64 tmp; cvta.to.shared.u64 tmp, %1; cvt.u32.u64 %0, tmp; }"
        : "=r"(addr) : "l"(smem_ptr));
    return addr;
}

__device__ __forceinline__ void ldm_x4(uint32_t* r, uint32_t addr) {
    asm volatile("ldmatrix.sync.aligned.m8n8.x4.shared.b16 {%0,%1,%2,%3}, [%4];"
        : "=r"(r[0]), "=r"(r[1]), "=r"(r[2]), "=r"(r[3]) : "r"(addr));
}

__device__ __forceinline__ void mma16816(float* c, const uint32_t* a, const uint32_t* b) {
    asm volatile(
        "mma.sync.aligned.m16n8k16.row.col.f32.bf16.bf16.f32 "
        "{%0,%1,%2,%3}, {%4,%5,%6,%7}, {%8,%9}, {%0,%1,%2,%3};"
        : "+f"(c[0]), "+f"(c[1]), "+f"(c[2]), "+f"(c[3])
        : "r"(a[0]), "r"(a[1]), "r"(a[2]), "r"(a[3]), "r"(b[0]), "r"(b[1]));
}

__global__ void __launch_bounds__(512, 1)
k_mm(const uint4* __restrict__ fhi, const uint4* __restrict__ flo,
     const uint4* __restrict__ w1hi, const uint4* __restrict__ w1lo,
     const uint4* __restrict__ w0hi, const uint4* __restrict__ w0lo,
     float* __restrict__ hout, float* __restrict__ rawout, int rowStart, int M) {
    extern __shared__ char smem[];
    const int tid = threadIdx.x;
    const int wid = tid >> 5;
    const int lane = tid & 31;
    const int ph = wid >> 3;       // 0: W1 -> hout, 1: W0 -> rawout
    const int w8 = wid & 7;
    const int wm = w8 >> 1;        // 0..3 : 32-row strip
    const int wn = w8 & 1;         // 0..1 : 64-col strip
    const int rowBase = rowStart + blockIdx.x * 128;

    const uint4 z4 = make_uint4(0, 0, 0, 0);
#pragma unroll 4
    for (int i = tid; i < 2048; i += 512) {
        int r = i >> 4, c = i & 15;
        uint32_t off = (uint32_t)r * SROW + (uint32_t)c * 16;
        bool ok = (rowBase + r) < M;
        size_t gi = (size_t)rowBase * 16 + i;
        *(uint4*)(smem + SM_A_HI + off) = ok ? fhi[gi] : z4;
        *(uint4*)(smem + SM_A_LO + off) = ok ? flo[gi] : z4;
        *(uint4*)(smem + SM_W1HI + off) = w1hi[i];
        *(uint4*)(smem + SM_W1LO + off) = w1lo[i];
        *(uint4*)(smem + SM_W0HI + off) = w0hi[i];
        *(uint4*)(smem + SM_W0LO + off) = w0lo[i];
    }
    __syncthreads();

    uint32_t sb = smem_to_u32(smem);
    const uint32_t aRowOff = (uint32_t)(wm * 32 + (lane & 15)) * SROW + ((lane >> 4) << 4);
    const uint32_t bRowCore = (uint32_t)(((lane >> 4) << 3) + (lane & 7)) * SROW
                            + (((lane >> 3) & 1) << 4);
    const int g = lane >> 2, tg = lane & 3;

    uint32_t wHi = sb + (ph ? SM_W0HI : SM_W1HI);
    uint32_t wLo = sb + (ph ? SM_W0LO : SM_W1LO);
    uint32_t aB0 = sb + SM_A_HI, aB1 = sb + SM_A_LO;

    float acc[2][8][4];
#pragma unroll
    for (int mt = 0; mt < 2; mt++)
#pragma unroll
        for (int nt = 0; nt < 8; nt++)
#pragma unroll
            for (int q = 0; q < 4; q++) acc[mt][nt][q] = 0.f;

#pragma unroll 1
    for (int t = 0; t < 3; t++) {
        uint32_t aT = (t == 2) ? aB1 : aB0;     // hi, hi, lo
        uint32_t wT = (t == 1) ? wLo : wHi;     // hi, lo, hi
#pragma unroll
        for (int ks = 0; ks < 8; ks++) {
            uint32_t kb = (uint32_t)ks * 32;
            uint32_t a[2][4];
            ldm_x4(a[0], aT + aRowOff + kb);
            ldm_x4(a[1], aT + aRowOff + 16 * SROW + kb);
            uint32_t b[8][2];
#pragma unroll
            for (int np = 0; np < 4; np++) {
                uint32_t tmp[4];
                ldm_x4(tmp, wT + (uint32_t)(wn * 64 + np * 16) * SROW + bRowCore + kb);
                b[np * 2][0] = tmp[0]; b[np * 2][1] = tmp[1];
                b[np * 2 + 1][0] = tmp[2]; b[np * 2 + 1][1] = tmp[3];
            }
#pragma unroll
            for (int mt = 0; mt < 2; mt++)
#pragma unroll
                for (int nt = 0; nt < 8; nt++)
                    mma16816(acc[mt][nt], a[mt], b[nt]);
        }
    }

    float* dst = ph ? rawout : hout;
#pragma unroll
    for (int mt = 0; mt < 2; mt++) {
        int row0 = rowBase + wm * 32 + mt * 16 + g;
#pragma unroll
        for (int nt = 0; nt < 8; nt++) {
            int col = wn * 64 + nt * 8 + tg * 2;
            if (row0 < M)
                *(float2*)(dst + (size_t)row0 * 128 + col) =
                    make_float2(acc[mt][nt][0], acc[mt][nt][1]);
            if (row0 + 8 < M)
                *(float2*)(dst + (size_t)(row0 + 8) * 128 + col) =
                    make_float2(acc[mt][nt][2], acc[mt][nt][3]);
        }
    }
}

// ============ fused aggregate + epilogue (+ next-layer bf16 split) ============
__device__ __forceinline__ void f4add(float4& a, const float4 b) {
    a.x += b.x; a.y += b.y; a.z += b.z; a.w += b.w;
}

__global__ void k_aggepi(const float4* __restrict__ h, const float4* __restrict__ raw,
                         const float* __restrict__ bias, const float4* __restrict__ res,
                         float4* __restrict__ outF,
                         uint2* __restrict__ fhi, uint2* __restrict__ flo,
                         int nodeStart, int nodeEnd, int mode) {
    int warp = nodeStart + ((blockIdx.x * blockDim.x + threadIdx.x) >> 5);
    if (warp >= nodeEnd) return;
    int lane = threadIdx.x & 31;
    int b = g_rowptr[warp], e = g_rowptr[warp + 1];
    float4 a0 = make_float4(0.f, 0.f, 0.f, 0.f);
    float4 a1 = a0, a2 = a0, a3 = a0;
    int p = b;
    for (; p + 4 <= e; p += 4) {
        int n0 = g_adj[p];
        int n1 = g_adj[p + 1];
        int n2 = g_adj[p + 2];
        int n3 = g_adj[p + 3];
        f4add(a0, h[(size_t)n0 * 32 + lane]);
        f4add(a1, h[(size_t)n1 * 32 + lane]);
        f4add(a2, h[(size_t)n2 * 32 + lane]);
        f4add(a3, h[(size_t)n3 * 32 + lane]);
    }
    for (; p < e; ++p) f4add(a0, h[(size_t)g_adj[p] * 32 + lane]);
    float s = g_invdeg[warp];

    size_t idx = (size_t)warp * 32 + lane;
    float4 v = raw[idx];
    float4 bb = ((const float4*)bias)[lane];
    v.x += bb.x + (a0.x + a1.x + a2.x + a3.x) * s;
    v.y += bb.y + (a0.y + a1.y + a2.y + a3.y) * s;
    v.z += bb.z + (a0.z + a1.z + a2.z + a3.z) * s;
    v.w += bb.w + (a0.w + a1.w + a2.w + a3.w) * s;
    if (mode == 2) {
        float4 r = res[idx];
        v.x += r.x; v.y += r.y; v.z += r.z; v.w += r.w;
    }
    if (mode >= 1) {
        v.x = fmaxf(v.x, 0.f); v.y = fmaxf(v.y, 0.f);
        v.z = fmaxf(v.z, 0.f); v.w = fmaxf(v.w, 0.f);
    }
    if (mode == 2) {
        outF[idx] = v;
    } else {
        uint2 hi, lo;
        split4(v, hi, lo);
        fhi[idx] = hi;
        flo[idx] = lo;
    }
}

// ======================= launch =======================
extern "C" void kernel_launch(void* const* d_in, const int* in_sizes, int n_in,
                              void* d_out, int out_size) {
    const float* features = (const float*)d_in[0];
    const int*   edges    = (const int*)d_in[1];
    const float* W0f = (const float*)d_in[3];
    const float* W1f = (const float*)d_in[4];
    const float* bf  = (const float*)d_in[5];
    const float* W0h = (const float*)d_in[6];
    const float* W1h = (const float*)d_in[7];
    const float* bh  = (const float*)d_in[8];

    int Nn = in_sizes[0] / D;
    int Ee = in_sizes[1] / 2;

    uint4 *fhi, *flo, *whi, *wlo;
    float4 *hbuf[2], *rawbuf[2];
    int* cntp;
    cudaGetSymbolAddress((void**)&fhi, g_fhi4);
    cudaGetSymbolAddress((void**)&flo, g_flo4);
    cudaGetSymbolAddress((void**)&whi, g_Whi4);
    cudaGetSymbolAddress((void**)&wlo, g_Wlo4);
    cudaGetSymbolAddress((void**)&hbuf[0],   g_hA);
    cudaGetSymbolAddress((void**)&hbuf[1],   g_hB);
    cudaGetSymbolAddress((void**)&rawbuf[0], g_rawA);
    cudaGetSymbolAddress((void**)&rawbuf[1], g_rawB);
    cudaGetSymbolAddress((void**)&cntp, g_cnt);

    cudaFuncSetAttribute(k_mm, cudaFuncAttributeMaxDynamicSharedMemorySize, SMEM_MM_TOTAL);

    const int totTiles = (Nn + 127) / 128;          // 391
    const int tilesP0 = (totTiles + 1) / 2;         // 196
    const int nodeSplit = (tilesP0 * 128 < Nn) ? tilesP0 * 128 : Nn;
    const int partStart[2] = {0, nodeSplit};
    const int partEnd[2]   = {nodeSplit, Nn};
    const int partTiles[2] = {tilesP0, totTiles - tilesP0};
    int vblocks = (Nn * 32 + 255) / 256;

    cudaStream_t s0 = (cudaStream_t)0;   // capture-origin stream
    cudaStream_t s1;
    cudaStreamCreateWithFlags(&s1, cudaStreamNonBlocking);

    cudaEvent_t evFork, evMM[4], evA[4][2];
    cudaEventCreateWithFlags(&evFork, cudaEventDisableTiming);
    for (int l = 0; l < 4; l++) {
        cudaEventCreateWithFlags(&evMM[l], cudaEventDisableTiming);
        cudaEventCreateWithFlags(&evA[l][0], cudaEventDisableTiming);
        cudaEventCreateWithFlags(&evA[l][1], cudaEventDisableTiming);
    }

    cudaEventRecord(evFork, s0);
    cudaStreamWaitEvent(s1, evFork, 0);

    // s0: conversion then full-width layer-0 GEMM (4th launch overall -> ncu slot)
    k_conv<<<vblocks, 256, 0, s0>>>(features, W0f, W1f, W0h, W1h, Nn);
    // s1: CSR build chain (independent of s0 until aggepi)
    cudaMemsetAsync(cntp, 0, (size_t)Nn * sizeof(int), s1);
    k_count<<<(Ee + 255) / 256, 256, 0, s1>>>(edges, Ee);
    k_scan<<<1, 1024, 0, s1>>>(Nn);
    k_mm<<<totTiles, 512, SMEM_MM_TOTAL, s0>>>(fhi, flo,
        whi + 0 * 2048, wlo + 0 * 2048,
        whi + 1 * 2048, wlo + 1 * 2048,
        (float*)hbuf[0], (float*)rawbuf[0], 0, Nn);
    cudaEventRecord(evMM[0], s0);
    k_fill<<<(Ee + 255) / 256, 256, 0, s1>>>(edges, Ee);
    k_sortseg<<<(Nn + 127) / 128, 128, 0, s1>>>(Nn);

    for (int l = 0; l < 4; l++) {
        float4* hrd = hbuf[l & 1];
        float4* rrd = rawbuf[l & 1];
        const float* bb = (l == 0) ? bf : bh + (size_t)(l - 1) * D;
        int mode = (l == 0) ? 0 : (l == 3 ? 2 : 1);

        cudaStreamWaitEvent(s1, evMM[l], 0);   // all h/raw of this layer ready
        for (int p = 0; p < 2; p++) {
            int ablocks = ((partEnd[p] - partStart[p]) * 32 + 255) / 256;
            k_aggepi<<<ablocks, 256, 0, s1>>>(hrd, rrd, bb, (const float4*)features,
                                              (float4*)d_out, (uint2*)fhi, (uint2*)flo,
                                              partStart[p], partEnd[p], mode);
            cudaEventRecord(evA[l][p], s1);
        }

        if (l < 3) {
            int nl = l + 1;
            float4* hwr = hbuf[nl & 1];
            float4* rwr = rawbuf[nl & 1];
            for (int p = 0; p < 2; p++) {
                cudaStreamWaitEvent(s0, evA[l][p], 0);
                k_mm<<<partTiles[p], 512, SMEM_MM_TOTAL, s0>>>(fhi, flo,
                    whi + (size_t)(2 * nl) * 2048,     wlo + (size_t)(2 * nl) * 2048,
                    whi + (size_t)(2 * nl + 1) * 2048, wlo + (size_t)(2 * nl + 1) * 2048,
                    (float*)hwr, (float*)rwr, partStart[p], Nn);
            }
            cudaEventRecord(evMM[nl], s0);
        }
    }

    // join s1 back into the capture-origin stream
    cudaStreamWaitEvent(s0, evA[3][1], 0);
}

// round 7
// speedup vs baseline: 1.2223x; 1.1121x over previous
#include <cuda_runtime.h>
#include <cuda_bf16.h>
#include <cuda_fp16.h>
#include <stdint.h>

#define NMAX 50000
#define EMAX 600000
#define D 128

// ======================= device scratch (no allocation) =======================
__device__ uint4  g_fhi4[NMAX * D / 8];       // bf16 hi of layer input
__device__ uint4  g_flo4[NMAX * D / 8];       // bf16 lo
__device__ uint4  g_Whi4[8 * D * D / 8];      // 8 weight matrices bf16 hi [l*2 + {0:W1,1:W0}]
__device__ uint4  g_Wlo4[8 * D * D / 8];
__device__ __half g_h[NMAX * D];              // h = f @ W1^T (fp16 — gather payload)
__device__ float4 g_raw[NMAX * D / 4];        // raw = f @ W0^T (fp32)
__device__ int    g_cnt[NMAX];
__device__ int    g_cursor[NMAX];
__device__ int    g_rowptr[NMAX + 1];
__device__ float  g_invdeg[NMAX];
__device__ int    g_adj[2 * EMAX];

// ======================= bf16 hi/lo split =======================
__device__ __forceinline__ void split4(float4 v, uint2& hi, uint2& lo) {
    __nv_bfloat16 hx = __float2bfloat16_rn(v.x);
    __nv_bfloat16 hy = __float2bfloat16_rn(v.y);
    __nv_bfloat16 hz = __float2bfloat16_rn(v.z);
    __nv_bfloat16 hw = __float2bfloat16_rn(v.w);
    __nv_bfloat16 lx = __float2bfloat16_rn(v.x - __bfloat162float(hx));
    __nv_bfloat16 ly = __float2bfloat16_rn(v.y - __bfloat162float(hy));
    __nv_bfloat16 lz = __float2bfloat16_rn(v.z - __bfloat162float(hz));
    __nv_bfloat16 lw = __float2bfloat16_rn(v.w - __bfloat162float(hw));
    __nv_bfloat162 h01 = __halves2bfloat162(hx, hy);
    __nv_bfloat162 h23 = __halves2bfloat162(hz, hw);
    __nv_bfloat162 l01 = __halves2bfloat162(lx, ly);
    __nv_bfloat162 l23 = __halves2bfloat162(lz, lw);
    hi.x = *(uint32_t*)&h01; hi.y = *(uint32_t*)&h23;
    lo.x = *(uint32_t*)&l01; lo.y = *(uint32_t*)&l23;
}

__global__ void k_conv(const float* __restrict__ features,
                       const float* __restrict__ W0f, const float* __restrict__ W1f,
                       const float* __restrict__ W0h, const float* __restrict__ W1h,
                       int Nn) {
    int i = blockIdx.x * blockDim.x + threadIdx.x;
    if (i < Nn * 32) {
        float4 v = ((const float4*)features)[i];
        uint2 hi, lo;
        split4(v, hi, lo);
        ((uint2*)g_fhi4)[i] = hi;
        ((uint2*)g_flo4)[i] = lo;
    }
    if (i < 8 * 4096) {
        int m = i >> 12;
        int off = i & 4095;
        int l = m >> 1;
        int isW0 = m & 1;
        const float* src = (l == 0) ? (isW0 ? W0f : W1f)
                                    : (isW0 ? W0h + (size_t)(l - 1) * D * D
                                            : W1h + (size_t)(l - 1) * D * D);
        float4 v = ((const float4*)src)[off];
        uint2 hi, lo;
        split4(v, hi, lo);
        ((uint2*)g_Whi4)[(size_t)m * 4096 + off] = hi;
        ((uint2*)g_Wlo4)[(size_t)m * 4096 + off] = lo;
    }
}

// ======================= CSR build =======================
__global__ void k_count(const int* __restrict__ edges, int E) {
    int e = blockIdx.x * blockDim.x + threadIdx.x;
    if (e < E) {
        atomicAdd(&g_cnt[edges[2 * e]], 1);
        atomicAdd(&g_cnt[edges[2 * e + 1]], 1);
    }
}

__global__ void k_scan(int n) {
    __shared__ int ss[1024];
    int t = threadIdx.x;
    int chunk = (n + 1023) >> 10;
    int b = t * chunk;
    int e = min(b + chunk, n);
    int s = 0;
    for (int i = b; i < e; i++) s += g_cnt[i];
    ss[t] = s;
    __syncthreads();
    for (int off = 1; off < 1024; off <<= 1) {
        int add = (t >= off) ? ss[t - off] : 0;
        __syncthreads();
        ss[t] += add;
        __syncthreads();
    }
    int run = (t == 0) ? 0 : ss[t - 1];
    for (int i = b; i < e; i++) {
        g_rowptr[i] = run;
        g_cursor[i] = run;
        int c = g_cnt[i];
        g_invdeg[i] = 1.0f / (float)(c > 0 ? c : 1);
        run += c;
    }
    if (t == 1023) g_rowptr[n] = ss[1023];
}

__global__ void k_fill(const int* __restrict__ edges, int E) {
    int e = blockIdx.x * blockDim.x + threadIdx.x;
    if (e < E) {
        int s = edges[2 * e];
        int d = edges[2 * e + 1];
        g_adj[atomicAdd(&g_cursor[s], 1)] = d;
        g_adj[atomicAdd(&g_cursor[d], 1)] = s;
    }
}

// per-node insertion sort -> deterministic float summation order across replays
__global__ void k_sortseg(int n) {
    int i = blockIdx.x * blockDim.x + threadIdx.x;
    if (i >= n) return;
    int b = g_rowptr[i], e = g_rowptr[i + 1];
    for (int j = b + 1; j < e; j++) {
        int key = g_adj[j];
        int k = j - 1;
        while (k >= b && g_adj[k] > key) { g_adj[k + 1] = g_adj[k]; --k; }
        g_adj[k + 1] = key;
    }
}

// ======================= tensor-core fused GEMM (mma.sync bf16) ================
// 512 threads: warps 0-7 compute h = A@W1^T (fp16 out), warps 8-15 raw = A@W0^T (fp32).
#define SROW 272
#define STILE (128 * SROW)
#define SM_A_HI  0
#define SM_A_LO  (STILE)
#define SM_W1HI  (2 * STILE)
#define SM_W1LO  (3 * STILE)
#define SM_W0HI  (4 * STILE)
#define SM_W0LO  (5 * STILE)
#define SMEM_MM_TOTAL (6 * STILE)          // 208896 B

__device__ __forceinline__ uint32_t smem_to_u32(const void* smem_ptr) {
    uint32_t addr;
    asm("{ .reg .u64 tmp; cvta.to.shared.u64 tmp, %1; cvt.u32.u64 %0, tmp; }"
        : "=r"(addr) : "l"(smem_ptr));
    return addr;
}

__device__ __forceinline__ void ldm_x4(uint32_t* r, uint32_t addr) {
    asm volatile("ldmatrix.sync.aligned.m8n8.x4.shared.b16 {%0,%1,%2,%3}, [%4];"
        : "=r"(r[0]), "=r"(r[1]), "=r"(r[2]), "=r"(r[3]) : "r"(addr));
}

__device__ __forceinline__ void mma16816(float* c, const uint32_t* a, const uint32_t* b) {
    asm volatile(
        "mma.sync.aligned.m16n8k16.row.col.f32.bf16.bf16.f32 "
        "{%0,%1,%2,%3}, {%4,%5,%6,%7}, {%8,%9}, {%0,%1,%2,%3};"
        : "+f"(c[0]), "+f"(c[1]), "+f"(c[2]), "+f"(c[3])
        : "r"(a[0]), "r"(a[1]), "r"(a[2]), "r"(a[3]), "r"(b[0]), "r"(b[1]));
}

__global__ void __launch_bounds__(512, 1)
k_mm(const uint4* __restrict__ fhi, const uint4* __restrict__ flo,
     const uint4* __restrict__ w1hi, const uint4* __restrict__ w1lo,
     const uint4* __restrict__ w0hi, const uint4* __restrict__ w0lo,
     __half* __restrict__ hout, float* __restrict__ rawout, int M) {
    extern __shared__ char smem[];
    const int tid = threadIdx.x;
    const int wid = tid >> 5;
    const int lane = tid & 31;
    const int ph = wid >> 3;       // 0: W1 -> hout(fp16), 1: W0 -> rawout(fp32)
    const int w8 = wid & 7;
    const int wm = w8 >> 1;
    const int wn = w8 & 1;
    const int rowBase = blockIdx.x * 128;

    const uint4 z4 = make_uint4(0, 0, 0, 0);
#pragma unroll 4
    for (int i = tid; i < 2048; i += 512) {
        int r = i >> 4, c = i & 15;
        uint32_t off = (uint32_t)r * SROW + (uint32_t)c * 16;
        bool ok = (rowBase + r) < M;
        size_t gi = (size_t)rowBase * 16 + i;
        *(uint4*)(smem + SM_A_HI + off) = ok ? fhi[gi] : z4;
        *(uint4*)(smem + SM_A_LO + off) = ok ? flo[gi] : z4;
        *(uint4*)(smem + SM_W1HI + off) = w1hi[i];
        *(uint4*)(smem + SM_W1LO + off) = w1lo[i];
        *(uint4*)(smem + SM_W0HI + off) = w0hi[i];
        *(uint4*)(smem + SM_W0LO + off) = w0lo[i];
    }
    __syncthreads();

    uint32_t sb = smem_to_u32(smem);
    const uint32_t aRowOff = (uint32_t)(wm * 32 + (lane & 15)) * SROW + ((lane >> 4) << 4);
    const uint32_t bRowCore = (uint32_t)(((lane >> 4) << 3) + (lane & 7)) * SROW
                            + (((lane >> 3) & 1) << 4);
    const int g = lane >> 2, tg = lane & 3;

    uint32_t wHi = sb + (ph ? SM_W0HI : SM_W1HI);
    uint32_t wLo = sb + (ph ? SM_W0LO : SM_W1LO);
    uint32_t aB0 = sb + SM_A_HI, aB1 = sb + SM_A_LO;

    float acc[2][8][4];
#pragma unroll
    for (int mt = 0; mt < 2; mt++)
#pragma unroll
        for (int nt = 0; nt < 8; nt++)
#pragma unroll
            for (int q = 0; q < 4; q++) acc[mt][nt][q] = 0.f;

#pragma unroll 1
    for (int t = 0; t < 3; t++) {
        uint32_t aT = (t == 2) ? aB1 : aB0;     // hi, hi, lo
        uint32_t wT = (t == 1) ? wLo : wHi;     // hi, lo, hi
#pragma unroll
        for (int ks = 0; ks < 8; ks++) {
            uint32_t kb = (uint32_t)ks * 32;
            uint32_t a[2][4];
            ldm_x4(a[0], aT + aRowOff + kb);
            ldm_x4(a[1], aT + aRowOff + 16 * SROW + kb);
            uint32_t b[8][2];
#pragma unroll
            for (int np = 0; np < 4; np++) {
                uint32_t tmp[4];
                ldm_x4(tmp, wT + (uint32_t)(wn * 64 + np * 16) * SROW + bRowCore + kb);
                b[np * 2][0] = tmp[0]; b[np * 2][1] = tmp[1];
                b[np * 2 + 1][0] = tmp[2]; b[np * 2 + 1][1] = tmp[3];
            }
#pragma unroll
            for (int mt = 0; mt < 2; mt++)
#pragma unroll
                for (int nt = 0; nt < 8; nt++)
                    mma16816(acc[mt][nt], a[mt], b[nt]);
        }
    }

#pragma unroll
    for (int mt = 0; mt < 2; mt++) {
        int row0 = rowBase + wm * 32 + mt * 16 + g;
#pragma unroll
        for (int nt = 0; nt < 8; nt++) {
            int col = wn * 64 + nt * 8 + tg * 2;
            if (ph == 0) {
                if (row0 < M)
                    *(__half2*)(hout + (size_t)row0 * 128 + col) =
                        __floats2half2_rn(acc[mt][nt][0], acc[mt][nt][1]);
                if (row0 + 8 < M)
                    *(__half2*)(hout + (size_t)(row0 + 8) * 128 + col) =
                        __floats2half2_rn(acc[mt][nt][2], acc[mt][nt][3]);
            } else {
                if (row0 < M)
                    *(float2*)(rawout + (size_t)row0 * 128 + col) =
                        make_float2(acc[mt][nt][0], acc[mt][nt][1]);
                if (row0 + 8 < M)
                    *(float2*)(rawout + (size_t)(row0 + 8) * 128 + col) =
                        make_float2(acc[mt][nt][2], acc[mt][nt][3]);
            }
        }
    }
}

// ============ fused aggregate (fp16 gather) + epilogue + next-layer split ============
__global__ void k_aggepi(const __half* __restrict__ h, const float4* __restrict__ raw,
                         const float* __restrict__ bias, const float4* __restrict__ res,
                         float4* __restrict__ outF,
                         uint2* __restrict__ fhi, uint2* __restrict__ flo,
                         int n, int mode) {
    int warp = (blockIdx.x * blockDim.x + threadIdx.x) >> 5;
    if (warp >= n) return;
    int lane = threadIdx.x & 31;
    int b = g_rowptr[warp], e = g_rowptr[warp + 1];
    float4 a0 = make_float4(0.f, 0.f, 0.f, 0.f);
    float4 a1 = a0, a2 = a0, a3 = a0;
    const int co = lane * 4;
    int p = b;
    for (; p + 4 <= e; p += 4) {
        uint2 u0 = *(const uint2*)(h + (size_t)g_adj[p]     * 128 + co);
        uint2 u1 = *(const uint2*)(h + (size_t)g_adj[p + 1] * 128 + co);
        uint2 u2 = *(const uint2*)(h + (size_t)g_adj[p + 2] * 128 + co);
        uint2 u3 = *(const uint2*)(h + (size_t)g_adj[p + 3] * 128 + co);
        float2 x, y;
        x = __half22float2(*(__half2*)&u0.x); y = __half22float2(*(__half2*)&u0.y);
        a0.x += x.x; a0.y += x.y; a0.z += y.x; a0.w += y.y;
        x = __half22float2(*(__half2*)&u1.x); y = __half22float2(*(__half2*)&u1.y);
        a1.x += x.x; a1.y += x.y; a1.z += y.x; a1.w += y.y;
        x = __half22float2(*(__half2*)&u2.x); y = __half22float2(*(__half2*)&u2.y);
        a2.x += x.x; a2.y += x.y; a2.z += y.x; a2.w += y.y;
        x = __half22float2(*(__half2*)&u3.x); y = __half22float2(*(__half2*)&u3.y);
        a3.x += x.x; a3.y += x.y; a3.z += y.x; a3.w += y.y;
    }
    for (; p < e; ++p) {
        uint2 u = *(const uint2*)(h + (size_t)g_adj[p] * 128 + co);
        float2 x = __half22float2(*(__half2*)&u.x);
        float2 y = __half22float2(*(__half2*)&u.y);
        a0.x += x.x; a0.y += x.y; a0.z += y.x; a0.w += y.y;
    }
    float s = g_invdeg[warp];

    size_t idx = (size_t)warp * 32 + lane;
    float4 v = raw[idx];
    float4 bb = ((const float4*)bias)[lane];
    v.x += bb.x + (a0.x + a1.x + a2.x + a3.x) * s;
    v.y += bb.y + (a0.y + a1.y + a2.y + a3.y) * s;
    v.z += bb.z + (a0.z + a1.z + a2.z + a3.z) * s;
    v.w += bb.w + (a0.w + a1.w + a2.w + a3.w) * s;
    if (mode == 2) {
        float4 r = res[idx];
        v.x += r.x; v.y += r.y; v.z += r.z; v.w += r.w;
    }
    if (mode >= 1) {
        v.x = fmaxf(v.x, 0.f); v.y = fmaxf(v.y, 0.f);
        v.z = fmaxf(v.z, 0.f); v.w = fmaxf(v.w, 0.f);
    }
    if (mode == 2) {
        outF[idx] = v;
    } else {
        uint2 hi, lo;
        split4(v, hi, lo);
        fhi[idx] = hi;
        flo[idx] = lo;
    }
}

// ======================= launch =======================
extern "C" void kernel_launch(void* const* d_in, const int* in_sizes, int n_in,
                              void* d_out, int out_size) {
    const float* features = (const float*)d_in[0];
    const int*   edges    = (const int*)d_in[1];
    const float* W0f = (const float*)d_in[3];
    const float* W1f = (const float*)d_in[4];
    const float* bf  = (const float*)d_in[5];
    const float* W0h = (const float*)d_in[6];
    const float* W1h = (const float*)d_in[7];
    const float* bh  = (const float*)d_in[8];

    int Nn = in_sizes[0] / D;
    int Ee = in_sizes[1] / 2;

    uint4 *fhi, *flo, *whi, *wlo;
    __half* hbuf;
    float4* rawb;
    int* cntp;
    cudaGetSymbolAddress((void**)&fhi, g_fhi4);
    cudaGetSymbolAddress((void**)&flo, g_flo4);
    cudaGetSymbolAddress((void**)&whi, g_Whi4);
    cudaGetSymbolAddress((void**)&wlo, g_Wlo4);
    cudaGetSymbolAddress((void**)&hbuf, g_h);
    cudaGetSymbolAddress((void**)&rawb, g_raw);
    cudaGetSymbolAddress((void**)&cntp, g_cnt);

    cudaFuncSetAttribute(k_mm, cudaFuncAttributeMaxDynamicSharedMemorySize, SMEM_MM_TOTAL);

    int vblocks = (Nn * 32 + 255) / 256;
    int gblocks = (Nn + 127) / 128;
    int ablocks = (Nn * 32 + 255) / 256;

    cudaStream_t s0 = (cudaStream_t)0;   // capture-origin stream
    cudaStream_t s1;
    cudaStreamCreateWithFlags(&s1, cudaStreamNonBlocking);

    cudaEvent_t evFork, evCSR;
    cudaEventCreateWithFlags(&evFork, cudaEventDisableTiming);
    cudaEventCreateWithFlags(&evCSR, cudaEventDisableTiming);

    cudaEventRecord(evFork, s0);
    cudaStreamWaitEvent(s1, evFork, 0);

    // s0: conv -> mm0 (serial); s1: CSR chain, overlapped
    k_conv<<<vblocks, 256, 0, s0>>>(features, W0f, W1f, W0h, W1h, Nn);
    cudaMemsetAsync(cntp, 0, (size_t)Nn * sizeof(int), s1);
    k_count<<<(Ee + 255) / 256, 256, 0, s1>>>(edges, Ee);
    k_scan<<<1, 1024, 0, s1>>>(Nn);
    k_mm<<<gblocks, 512, SMEM_MM_TOTAL, s0>>>(fhi, flo,
        whi + 0 * 2048, wlo + 0 * 2048,
        whi + 1 * 2048, wlo + 1 * 2048,
        hbuf, (float*)rawb, Nn);
    k_fill<<<(Ee + 255) / 256, 256, 0, s1>>>(edges, Ee);
    k_sortseg<<<(Nn + 127) / 128, 128, 0, s1>>>(Nn);
    cudaEventRecord(evCSR, s1);
    cudaStreamWaitEvent(s0, evCSR, 0);   // join: aggepi needs the CSR

    for (int l = 0; l < 4; l++) {
        if (l > 0) {
            k_mm<<<gblocks, 512, SMEM_MM_TOTAL, s0>>>(fhi, flo,
                whi + (size_t)(2 * l) * 2048,     wlo + (size_t)(2 * l) * 2048,
                whi + (size_t)(2 * l + 1) * 2048, wlo + (size_t)(2 * l + 1) * 2048,
                hbuf, (float*)rawb, Nn);
        }
        const float* bb = (l == 0) ? bf : bh + (size_t)(l - 1) * D;
        int mode = (l == 0) ? 0 : (l == 3 ? 2 : 1);
        k_aggepi<<<ablocks, 256, 0, s0>>>(hbuf, rawb, bb, (const float4*)features,
                                          (float4*)d_out, (uint2*)fhi, (uint2*)flo, Nn, mode);
    }
}

// round 8
// speedup vs baseline: 1.2401x; 1.0145x over previous
#include <cuda_runtime.h>
#include <cuda_bf16.h>
#include <cuda_fp16.h>
#include <stdint.h>

#define NMAX 50000
#define EMAX 600000
#define D 128

// ======================= device scratch (no allocation) =======================
__device__ uint4  g_fhi4[NMAX * D / 8];       // bf16 hi of layer input
__device__ uint4  g_flo4[NMAX * D / 8];       // bf16 lo
__device__ uint4  g_Whi4[8 * D * D / 8];      // 8 weight matrices bf16 hi [l*2 + {0:W1,1:W0}]
__device__ uint4  g_Wlo4[8 * D * D / 8];
__device__ __half g_h[NMAX * D];              // h = f @ W1^T (fp16 — gather payload)
__device__ float4 g_raw[NMAX * D / 4];        // raw = f @ W0^T (fp32)
__device__ int    g_cnt[NMAX];
__device__ int    g_cursor[NMAX];
__device__ int    g_rowptr[NMAX + 1];
__device__ float  g_invdeg[NMAX];
__device__ int    g_adj[2 * EMAX];

// ======================= bf16 hi/lo split =======================
__device__ __forceinline__ void split4(float4 v, uint2& hi, uint2& lo) {
    __nv_bfloat16 hx = __float2bfloat16_rn(v.x);
    __nv_bfloat16 hy = __float2bfloat16_rn(v.y);
    __nv_bfloat16 hz = __float2bfloat16_rn(v.z);
    __nv_bfloat16 hw = __float2bfloat16_rn(v.w);
    __nv_bfloat16 lx = __float2bfloat16_rn(v.x - __bfloat162float(hx));
    __nv_bfloat16 ly = __float2bfloat16_rn(v.y - __bfloat162float(hy));
    __nv_bfloat16 lz = __float2bfloat16_rn(v.z - __bfloat162float(hz));
    __nv_bfloat16 lw = __float2bfloat16_rn(v.w - __bfloat162float(hw));
    __nv_bfloat162 h01 = __halves2bfloat162(hx, hy);
    __nv_bfloat162 h23 = __halves2bfloat162(hz, hw);
    __nv_bfloat162 l01 = __halves2bfloat162(lx, ly);
    __nv_bfloat162 l23 = __halves2bfloat162(lz, lw);
    hi.x = *(uint32_t*)&h01; hi.y = *(uint32_t*)&h23;
    lo.x = *(uint32_t*)&l01; lo.y = *(uint32_t*)&l23;
}

__device__ __forceinline__ void split2(float a, float b, uint32_t& hi, uint32_t& lo) {
    __nv_bfloat16 ha = __float2bfloat16_rn(a), hb = __float2bfloat16_rn(b);
    float ra = a - __bfloat162float(ha), rb = b - __bfloat162float(hb);
    __nv_bfloat162 H = __halves2bfloat162(ha, hb);
    __nv_bfloat162 L = __halves2bfloat162(__float2bfloat16_rn(ra), __float2bfloat16_rn(rb));
    hi = *(uint32_t*)&H;
    lo = *(uint32_t*)&L;
}

__global__ void k_conv(const float* __restrict__ features,
                       const float* __restrict__ W0f, const float* __restrict__ W1f,
                       const float* __restrict__ W0h, const float* __restrict__ W1h,
                       int Nn) {
    int i = blockIdx.x * blockDim.x + threadIdx.x;
    if (i < Nn * 32) {
        float4 v = ((const float4*)features)[i];
        uint2 hi, lo;
        split4(v, hi, lo);
        ((uint2*)g_fhi4)[i] = hi;
        ((uint2*)g_flo4)[i] = lo;
    }
    if (i < 8 * 4096) {
        int m = i >> 12;
        int off = i & 4095;
        int l = m >> 1;
        int isW0 = m & 1;
        const float* src = (l == 0) ? (isW0 ? W0f : W1f)
                                    : (isW0 ? W0h + (size_t)(l - 1) * D * D
                                            : W1h + (size_t)(l - 1) * D * D);
        float4 v = ((const float4*)src)[off];
        uint2 hi, lo;
        split4(v, hi, lo);
        ((uint2*)g_Whi4)[(size_t)m * 4096 + off] = hi;
        ((uint2*)g_Wlo4)[(size_t)m * 4096 + off] = lo;
    }
}

// ======================= CSR build =======================
__global__ void k_count(const int* __restrict__ edges, int E) {
    int e = blockIdx.x * blockDim.x + threadIdx.x;
    if (e < E) {
        atomicAdd(&g_cnt[edges[2 * e]], 1);
        atomicAdd(&g_cnt[edges[2 * e + 1]], 1);
    }
}

__global__ void k_scan(int n) {
    __shared__ int ss[1024];
    int t = threadIdx.x;
    int chunk = (n + 1023) >> 10;
    int b = t * chunk;
    int e = min(b + chunk, n);
    int s = 0;
    for (int i = b; i < e; i++) s += g_cnt[i];
    ss[t] = s;
    __syncthreads();
    for (int off = 1; off < 1024; off <<= 1) {
        int add = (t >= off) ? ss[t - off] : 0;
        __syncthreads();
        ss[t] += add;
        __syncthreads();
    }
    int run = (t == 0) ? 0 : ss[t - 1];
    for (int i = b; i < e; i++) {
        g_rowptr[i] = run;
        g_cursor[i] = run;
        int c = g_cnt[i];
        g_invdeg[i] = 1.0f / (float)(c > 0 ? c : 1);
        run += c;
    }
    if (t == 1023) g_rowptr[n] = ss[1023];
}

__global__ void k_fill(const int* __restrict__ edges, int E) {
    int e = blockIdx.x * blockDim.x + threadIdx.x;
    if (e < E) {
        int s = edges[2 * e];
        int d = edges[2 * e + 1];
        g_adj[atomicAdd(&g_cursor[s], 1)] = d;
        g_adj[atomicAdd(&g_cursor[d], 1)] = s;
    }
}

// deterministic adjacency order: per-node sort, staged through local memory
#define SORT_BUF 96
__global__ void k_sortseg(int n) {
    int i = blockIdx.x * blockDim.x + threadIdx.x;
    if (i >= n) return;
    int b = g_rowptr[i], e = g_rowptr[i + 1];
    int len = e - b;
    if (len <= 1) return;
    if (len <= SORT_BUF) {
        int buf[SORT_BUF];
        for (int j = 0; j < len; j++) buf[j] = g_adj[b + j];
        for (int j = 1; j < len; j++) {
            int key = buf[j];
            int k = j - 1;
            while (k >= 0 && buf[k] > key) { buf[k + 1] = buf[k]; --k; }
            buf[k + 1] = key;
        }
        for (int j = 0; j < len; j++) g_adj[b + j] = buf[j];
    } else {
        for (int j = b + 1; j < e; j++) {
            int key = g_adj[j];
            int k = j - 1;
            while (k >= b && g_adj[k] > key) { g_adj[k + 1] = g_adj[k]; --k; }
            g_adj[k + 1] = key;
        }
    }
}

// ======================= tensor-core fused GEMM (mma.sync bf16) ================
// 512 threads: warps 0-7 compute h = A@W1^T (fp16 out), warps 8-15 raw = A@W0^T (fp32).
// Per ks-step: load Ahi/Alo/Bhi/Blo frags ONCE, issue all 3 split terms (48 MMA).
#define SROW 272
#define STILE (128 * SROW)
#define SM_A_HI  0
#define SM_A_LO  (STILE)
#define SM_W1HI  (2 * STILE)
#define SM_W1LO  (3 * STILE)
#define SM_W0HI  (4 * STILE)
#define SM_W0LO  (5 * STILE)
#define SMEM_MM_TOTAL (6 * STILE)          // 208896 B

__device__ __forceinline__ uint32_t smem_to_u32(const void* smem_ptr) {
    uint32_t addr;
    asm("{ .reg .u64 tmp; cvta.to.shared.u64 tmp, %1; cvt.u32.u64 %0, tmp; }"
        : "=r"(addr) : "l"(smem_ptr));
    return addr;
}

__device__ __forceinline__ void ldm_x4(uint32_t* r, uint32_t addr) {
    asm volatile("ldmatrix.sync.aligned.m8n8.x4.shared.b16 {%0,%1,%2,%3}, [%4];"
        : "=r"(r[0]), "=r"(r[1]), "=r"(r[2]), "=r"(r[3]) : "r"(addr));
}

__device__ __forceinline__ void mma16816(float* c, const uint32_t* a, const uint32_t* b) {
    asm volatile(
        "mma.sync.aligned.m16n8k16.row.col.f32.bf16.bf16.f32 "
        "{%0,%1,%2,%3}, {%4,%5,%6,%7}, {%8,%9}, {%0,%1,%2,%3};"
        : "+f"(c[0]), "+f"(c[1]), "+f"(c[2]), "+f"(c[3])
        : "r"(a[0]), "r"(a[1]), "r"(a[2]), "r"(a[3]), "r"(b[0]), "r"(b[1]));
}

__global__ void __launch_bounds__(512, 1)
k_mm(const uint4* __restrict__ fhi, const uint4* __restrict__ flo,
     const uint4* __restrict__ w1hi, const uint4* __restrict__ w1lo,
     const uint4* __restrict__ w0hi, const uint4* __restrict__ w0lo,
     __half* __restrict__ hout, float* __restrict__ rawout, int M) {
    extern __shared__ char smem[];
    const int tid = threadIdx.x;
    const int wid = tid >> 5;
    const int lane = tid & 31;
    const int ph = wid >> 3;       // 0: W1 -> hout(fp16), 1: W0 -> rawout(fp32)
    const int w8 = wid & 7;
    const int wm = w8 >> 1;
    const int wn = w8 & 1;
    const int rowBase = blockIdx.x * 128;

    const uint4 z4 = make_uint4(0, 0, 0, 0);
#pragma unroll 4
    for (int i = tid; i < 2048; i += 512) {
        int r = i >> 4, c = i & 15;
        uint32_t off = (uint32_t)r * SROW + (uint32_t)c * 16;
        bool ok = (rowBase + r) < M;
        size_t gi = (size_t)rowBase * 16 + i;
        *(uint4*)(smem + SM_A_HI + off) = ok ? fhi[gi] : z4;
        *(uint4*)(smem + SM_A_LO + off) = ok ? flo[gi] : z4;
        *(uint4*)(smem + SM_W1HI + off) = w1hi[i];
        *(uint4*)(smem + SM_W1LO + off) = w1lo[i];
        *(uint4*)(smem + SM_W0HI + off) = w0hi[i];
        *(uint4*)(smem + SM_W0LO + off) = w0lo[i];
    }
    __syncthreads();

    uint32_t sb = smem_to_u32(smem);
    const uint32_t aRowOff = (uint32_t)(wm * 32 + (lane & 15)) * SROW + ((lane >> 4) << 4);
    const uint32_t bRowCore = (uint32_t)(((lane >> 4) << 3) + (lane & 7)) * SROW
                            + (((lane >> 3) & 1) << 4);
    const int g = lane >> 2, tg = lane & 3;

    uint32_t wHi = sb + (ph ? SM_W0HI : SM_W1HI);
    uint32_t wLo = sb + (ph ? SM_W0LO : SM_W1LO);
    uint32_t aHiB = sb + SM_A_HI, aLoB = sb + SM_A_LO;

    float acc[2][8][4];
#pragma unroll
    for (int mt = 0; mt < 2; mt++)
#pragma unroll
        for (int nt = 0; nt < 8; nt++)
#pragma unroll
            for (int q = 0; q < 4; q++) acc[mt][nt][q] = 0.f;

#pragma unroll 1
    for (int ks = 0; ks < 8; ks++) {
        uint32_t kb = (uint32_t)ks * 32;
        uint32_t aH[2][4], aL[2][4];
        ldm_x4(aH[0], aHiB + aRowOff + kb);
        ldm_x4(aH[1], aHiB + aRowOff + 16 * SROW + kb);
        ldm_x4(aL[0], aLoB + aRowOff + kb);
        ldm_x4(aL[1], aLoB + aRowOff + 16 * SROW + kb);
        uint32_t bH[8][2], bL[8][2];
#pragma unroll
        for (int np = 0; np < 4; np++) {
            uint32_t rowoff = (uint32_t)(wn * 64 + np * 16) * SROW + bRowCore + kb;
            uint32_t tmp[4];
            ldm_x4(tmp, wHi + rowoff);
            bH[np * 2][0] = tmp[0]; bH[np * 2][1] = tmp[1];
            bH[np * 2 + 1][0] = tmp[2]; bH[np * 2 + 1][1] = tmp[3];
            ldm_x4(tmp, wLo + rowoff);
            bL[np * 2][0] = tmp[0]; bL[np * 2][1] = tmp[1];
            bL[np * 2 + 1][0] = tmp[2]; bL[np * 2 + 1][1] = tmp[3];
        }
#pragma unroll
        for (int mt = 0; mt < 2; mt++)
#pragma unroll
            for (int nt = 0; nt < 8; nt++) {
                mma16816(acc[mt][nt], aH[mt], bH[nt]);   // hi*hi
                mma16816(acc[mt][nt], aH[mt], bL[nt]);   // hi*lo
                mma16816(acc[mt][nt], aL[mt], bH[nt]);   // lo*hi
            }
    }

#pragma unroll
    for (int mt = 0; mt < 2; mt++) {
        int row0 = rowBase + wm * 32 + mt * 16 + g;
#pragma unroll
        for (int nt = 0; nt < 8; nt++) {
            int col = wn * 64 + nt * 8 + tg * 2;
            if (ph == 0) {
                if (row0 < M)
                    *(__half2*)(hout + (size_t)row0 * 128 + col) =
                        __floats2half2_rn(acc[mt][nt][0], acc[mt][nt][1]);
                if (row0 + 8 < M)
                    *(__half2*)(hout + (size_t)(row0 + 8) * 128 + col) =
                        __floats2half2_rn(acc[mt][nt][2], acc[mt][nt][3]);
            } else {
                if (row0 < M)
                    *(float2*)(rawout + (size_t)row0 * 128 + col) =
                        make_float2(acc[mt][nt][0], acc[mt][nt][1]);
                if (row0 + 8 < M)
                    *(float2*)(rawout + (size_t)(row0 + 8) * 128 + col) =
                        make_float2(acc[mt][nt][2], acc[mt][nt][3]);
            }
        }
    }
}

// ============ fused aggregate (fp16 gather) + epilogue + next-layer split ============
// TWO warps per node: warp-half hw handles columns [hw*64, hw*64+64), 2 halves/lane.
__global__ void k_aggepi(const __half* __restrict__ h, const float* __restrict__ raw,
                         const float* __restrict__ bias, const float* __restrict__ res,
                         float* __restrict__ outF,
                         uint32_t* __restrict__ fhi, uint32_t* __restrict__ flo,
                         int n, int mode) {
    int gw = (blockIdx.x * blockDim.x + threadIdx.x) >> 5;
    int node = gw >> 1;
    if (node >= n) return;
    int hw = gw & 1;
    int lane = threadIdx.x & 31;
    int co = hw * 64 + lane * 2;   // column offset (halves)
    int b = g_rowptr[node], e = g_rowptr[node + 1];

    float2 a0 = make_float2(0.f, 0.f), a1 = a0, a2 = a0, a3 = a0;
    int p = b;
    for (; p + 4 <= e; p += 4) {
        uint32_t u0 = *(const uint32_t*)(h + (size_t)g_adj[p]     * 128 + co);
        uint32_t u1 = *(const uint32_t*)(h + (size_t)g_adj[p + 1] * 128 + co);
        uint32_t u2 = *(const uint32_t*)(h + (size_t)g_adj[p + 2] * 128 + co);
        uint32_t u3 = *(const uint32_t*)(h + (size_t)g_adj[p + 3] * 128 + co);
        float2 x;
        x = __half22float2(*(__half2*)&u0); a0.x += x.x; a0.y += x.y;
        x = __half22float2(*(__half2*)&u1); a1.x += x.x; a1.y += x.y;
        x = __half22float2(*(__half2*)&u2); a2.x += x.x; a2.y += x.y;
        x = __half22float2(*(__half2*)&u3); a3.x += x.x; a3.y += x.y;
    }
    for (; p < e; ++p) {
        uint32_t u = *(const uint32_t*)(h + (size_t)g_adj[p] * 128 + co);
        float2 x = __half22float2(*(__half2*)&u);
        a0.x += x.x; a0.y += x.y;
    }
    float s = g_invdeg[node];

    size_t base = (size_t)node * 128 + co;
    float v0 = raw[base]     + bias[co]     + (a0.x + a1.x + a2.x + a3.x) * s;
    float v1 = raw[base + 1] + bias[co + 1] + (a0.y + a1.y + a2.y + a3.y) * s;
    if (mode == 2) {
        v0 += res[base];
        v1 += res[base + 1];
    }
    if (mode >= 1) { v0 = fmaxf(v0, 0.f); v1 = fmaxf(v1, 0.f); }
    if (mode == 2) {
        *(float2*)(outF + base) = make_float2(v0, v1);
    } else {
        uint32_t hi, lo;
        split2(v0, v1, hi, lo);
        fhi[base >> 1] = hi;
        flo[base >> 1] = lo;
    }
}

// ======================= launch =======================
extern "C" void kernel_launch(void* const* d_in, const int* in_sizes, int n_in,
                              void* d_out, int out_size) {
    const float* features = (const float*)d_in[0];
    const int*   edges    = (const int*)d_in[1];
    const float* W0f = (const float*)d_in[3];
    const float* W1f = (const float*)d_in[4];
    const float* bf  = (const float*)d_in[5];
    const float* W0h = (const float*)d_in[6];
    const float* W1h = (const float*)d_in[7];
    const float* bh  = (const float*)d_in[8];

    int Nn = in_sizes[0] / D;
    int Ee = in_sizes[1] / 2;

    uint4 *fhi, *flo, *whi, *wlo;
    __half* hbuf;
    float4* rawb;
    int* cntp;
    cudaGetSymbolAddress((void**)&fhi, g_fhi4);
    cudaGetSymbolAddress((void**)&flo, g_flo4);
    cudaGetSymbolAddress((void**)&whi, g_Whi4);
    cudaGetSymbolAddress((void**)&wlo, g_Wlo4);
    cudaGetSymbolAddress((void**)&hbuf, g_h);
    cudaGetSymbolAddress((void**)&rawb, g_raw);
    cudaGetSymbolAddress((void**)&cntp, g_cnt);

    cudaFuncSetAttribute(k_mm, cudaFuncAttributeMaxDynamicSharedMemorySize, SMEM_MM_TOTAL);

    int vblocks = (Nn * 32 + 255) / 256;
    int gblocks = (Nn + 127) / 128;
    int ablocks = (Nn * 64 + 255) / 256;    // 2 warps per node

    cudaStream_t s0 = (cudaStream_t)0;   // capture-origin stream
    cudaStream_t s1;
    cudaStreamCreateWithFlags(&s1, cudaStreamNonBlocking);

    cudaEvent_t evFork, evCSR;
    cudaEventCreateWithFlags(&evFork, cudaEventDisableTiming);
    cudaEventCreateWithFlags(&evCSR, cudaEventDisableTiming);

    cudaEventRecord(evFork, s0);
    cudaStreamWaitEvent(s1, evFork, 0);

    // s0: conv -> mm0 (serial); s1: CSR chain, overlapped
    k_conv<<<vblocks, 256, 0, s0>>>(features, W0f, W1f, W0h, W1h, Nn);
    cudaMemsetAsync(cntp, 0, (size_t)Nn * sizeof(int), s1);
    k_count<<<(Ee + 255) / 256, 256, 0, s1>>>(edges, Ee);
    k_scan<<<1, 1024, 0, s1>>>(Nn);
    k_mm<<<gblocks, 512, SMEM_MM_TOTAL, s0>>>(fhi, flo,
        whi + 0 * 2048, wlo + 0 * 2048,
        whi + 1 * 2048, wlo + 1 * 2048,
        hbuf, (float*)rawb, Nn);
    k_fill<<<(Ee + 255) / 256, 256, 0, s1>>>(edges, Ee);
    k_sortseg<<<(Nn + 127) / 128, 128, 0, s1>>>(Nn);
    cudaEventRecord(evCSR, s1);
    cudaStreamWaitEvent(s0, evCSR, 0);   // join: aggepi needs the CSR

    for (int l = 0; l < 4; l++) {
        if (l > 0) {
            k_mm<<<gblocks, 512, SMEM_MM_TOTAL, s0>>>(fhi, flo,
                whi + (size_t)(2 * l) * 2048,     wlo + (size_t)(2 * l) * 2048,
                whi + (size_t)(2 * l + 1) * 2048, wlo + (size_t)(2 * l + 1) * 2048,
                hbuf, (float*)rawb, Nn);
        }
        const float* bb = (l == 0) ? bf : bh + (size_t)(l - 1) * D;
        int mode = (l == 0) ? 0 : (l == 3 ? 2 : 1);
        k_aggepi<<<ablocks, 256, 0, s0>>>(hbuf, (const float*)rawb, bb, features,
                                          (float*)d_out, (uint32_t*)fhi, (uint32_t*)flo,
                                          Nn, mode);
    }
}